// round 1
// baseline (speedup 1.0000x reference)
#include <cuda_runtime.h>

// OrdLoss: sum over valid voxels of [k<=t]*log(clip(p)) + [k>t]*log(clip(1-p)),
// divided by -count(valid). pred [N,C,D,H,W] f32, target [N,C,D,H,W] i32
// (replicated over C -> read channel 0 only), mask [N,1,D,H,W] i32.

#define N_      2
#define C_      16
#define D_      32
#define H_      128
#define W_      128
#define MSP     (D_ * H_ * W_)        // 524288 voxels per batch item
#define NVOX    (N_ * MSP)            // 1048576 total voxels
#define NGROUPS (NVOX / 4)            // 262144 float4/int4 groups
#define BLOCKS  1024
#define THREADS 256
// BLOCKS*THREADS == NGROUPS exactly

__device__ float g_partial[BLOCKS];
__device__ int   g_count[BLOCKS];

__device__ __forceinline__ float clog(float q) {
    // log(clip(q, 1e-8, 1e8)); MUFU lg2-based fast log
    return __logf(fminf(fmaxf(q, 1e-8f), 1e8f));
}

__global__ void __launch_bounds__(THREADS)
ord_loss_main(const float* __restrict__ pred,
              const int*   __restrict__ target,
              const int*   __restrict__ mask)
{
    const int g = blockIdx.x * THREADS + threadIdx.x;  // group of 4 voxels
    const int m = g * 4;                                // first voxel index
    const int n = m >> 19;                              // MSP == 2^19
    const int base = m + n * (C_ - 1) * MSP;            // n*C*MSP + s (channel 0)

    const int4 mk = *reinterpret_cast<const int4*>(mask + m);
    const int4 tg = *reinterpret_cast<const int4*>(target + base);

    const float v0 = (mk.x > 0) ? 1.0f : 0.0f;
    const float v1 = (mk.y > 0) ? 1.0f : 0.0f;
    const float v2 = (mk.z > 0) ? 1.0f : 0.0f;
    const float v3 = (mk.w > 0) ? 1.0f : 0.0f;
    int cnt = (mk.x > 0) + (mk.y > 0) + (mk.z > 0) + (mk.w > 0);

    float a0 = 0.0f, a1 = 0.0f, a2 = 0.0f, a3 = 0.0f;

#pragma unroll
    for (int k = 0; k < C_; ++k) {
        const float4 p = *reinterpret_cast<const float4*>(pred + base + k * MSP);
        const float q0 = (k <= tg.x) ? p.x : (1.0f - p.x);
        const float q1 = (k <= tg.y) ? p.y : (1.0f - p.y);
        const float q2 = (k <= tg.z) ? p.z : (1.0f - p.z);
        const float q3 = (k <= tg.w) ? p.w : (1.0f - p.w);
        a0 += v0 * clog(q0);
        a1 += v1 * clog(q1);
        a2 += v2 * clog(q2);
        a3 += v3 * clog(q3);
    }

    float a = (a0 + a1) + (a2 + a3);

    // warp reduce
#pragma unroll
    for (int off = 16; off > 0; off >>= 1) {
        a   += __shfl_xor_sync(0xFFFFFFFFu, a, off);
        cnt += __shfl_xor_sync(0xFFFFFFFFu, cnt, off);
    }

    __shared__ float sa[THREADS / 32];
    __shared__ int   sc[THREADS / 32];
    const int wid = threadIdx.x >> 5;
    const int lid = threadIdx.x & 31;
    if (lid == 0) { sa[wid] = a; sc[wid] = cnt; }
    __syncthreads();

    if (wid == 0) {
        float aa = (lid < THREADS / 32) ? sa[lid] : 0.0f;
        int   cc = (lid < THREADS / 32) ? sc[lid] : 0;
#pragma unroll
        for (int off = 4; off > 0; off >>= 1) {
            aa += __shfl_xor_sync(0xFFFFFFFFu, aa, off);
            cc += __shfl_xor_sync(0xFFFFFFFFu, cc, off);
        }
        if (lid == 0) { g_partial[blockIdx.x] = aa; g_count[blockIdx.x] = cc; }
    }
}

__global__ void __launch_bounds__(THREADS)
ord_loss_final(float* __restrict__ out)
{
    float s = 0.0f;
    int   c = 0;
    for (int i = threadIdx.x; i < BLOCKS; i += THREADS) {
        s += g_partial[i];
        c += g_count[i];
    }
#pragma unroll
    for (int off = 16; off > 0; off >>= 1) {
        s += __shfl_xor_sync(0xFFFFFFFFu, s, off);
        c += __shfl_xor_sync(0xFFFFFFFFu, c, off);
    }
    __shared__ float sa[THREADS / 32];
    __shared__ int   sc[THREADS / 32];
    const int wid = threadIdx.x >> 5;
    const int lid = threadIdx.x & 31;
    if (lid == 0) { sa[wid] = s; sc[wid] = c; }
    __syncthreads();
    if (wid == 0) {
        float ss = (lid < THREADS / 32) ? sa[lid] : 0.0f;
        int   cc = (lid < THREADS / 32) ? sc[lid] : 0;
#pragma unroll
        for (int off = 4; off > 0; off >>= 1) {
            ss += __shfl_xor_sync(0xFFFFFFFFu, ss, off);
            cc += __shfl_xor_sync(0xFFFFFFFFu, cc, off);
        }
        if (lid == 0) out[0] = -ss / (float)cc;
    }
}

extern "C" void kernel_launch(void* const* d_in, const int* in_sizes, int n_in,
                              void* d_out, int out_size)
{
    const float* pred   = (const float*)d_in[0];
    const int*   target = (const int*)d_in[1];
    const int*   mask   = (const int*)d_in[2];
    float*       out    = (float*)d_out;

    ord_loss_main<<<BLOCKS, THREADS>>>(pred, target, mask);
    ord_loss_final<<<1, THREADS>>>(out);
}

// round 2
// speedup vs baseline: 1.0892x; 1.0892x over previous
#include <cuda_runtime.h>

// OrdLoss: sum over valid voxels of [k<=t]*log(clip(p)) + [k>t]*log(clip(1-p)),
// divided by -count(valid). pred [N,C,D,H,W] f32, target [N,C,D,H,W] i32
// (replicated over C -> read channel 0 only), mask [N,1,D,H,W] i32.
// Single kernel: per-block partials + last-block-done final reduction
// (deterministic: fixed-order sum over the partial array).

#define N_      2
#define C_      16
#define D_      32
#define H_      128
#define W_      128
#define MSP     (D_ * H_ * W_)        // 524288 voxels per batch item
#define NVOX    (N_ * MSP)            // 1048576 total voxels
#define NGROUPS (NVOX / 4)            // 262144 float4/int4 groups
#define BLOCKS  1024
#define THREADS 256
// BLOCKS*THREADS == NGROUPS exactly

__device__ float g_partial[BLOCKS];
__device__ int   g_count[BLOCKS];
__device__ unsigned int g_ticket = 0;   // zero-init; reset by last block each run

__device__ __forceinline__ float clog(float q) {
    // log(clip(q, 1e-8, 1e8)); MUFU lg2-based fast log
    return __logf(fminf(fmaxf(q, 1e-8f), 1e8f));
}

__global__ void __launch_bounds__(THREADS)
ord_loss_fused(const float* __restrict__ pred,
               const int*   __restrict__ target,
               const int*   __restrict__ mask,
               float*       __restrict__ out)
{
    const int g = blockIdx.x * THREADS + threadIdx.x;  // group of 4 voxels
    const int m = g * 4;                                // first voxel index
    const int n = m >> 19;                              // MSP == 2^19
    const int base = m + n * (C_ - 1) * MSP;            // n*C*MSP + s (channel 0)

    const int4 mk = *reinterpret_cast<const int4*>(mask + m);
    const int4 tg = *reinterpret_cast<const int4*>(target + base);

    const float v0 = (mk.x > 0) ? 1.0f : 0.0f;
    const float v1 = (mk.y > 0) ? 1.0f : 0.0f;
    const float v2 = (mk.z > 0) ? 1.0f : 0.0f;
    const float v3 = (mk.w > 0) ? 1.0f : 0.0f;
    int cnt = (mk.x > 0) + (mk.y > 0) + (mk.z > 0) + (mk.w > 0);

    float a0 = 0.0f, a1 = 0.0f, a2 = 0.0f, a3 = 0.0f;

#pragma unroll
    for (int k = 0; k < C_; ++k) {
        const float4 p = *reinterpret_cast<const float4*>(pred + base + k * MSP);
        const float q0 = (k <= tg.x) ? p.x : (1.0f - p.x);
        const float q1 = (k <= tg.y) ? p.y : (1.0f - p.y);
        const float q2 = (k <= tg.z) ? p.z : (1.0f - p.z);
        const float q3 = (k <= tg.w) ? p.w : (1.0f - p.w);
        a0 += v0 * clog(q0);
        a1 += v1 * clog(q1);
        a2 += v2 * clog(q2);
        a3 += v3 * clog(q3);
    }

    float a = (a0 + a1) + (a2 + a3);

    // warp reduce
#pragma unroll
    for (int off = 16; off > 0; off >>= 1) {
        a   += __shfl_xor_sync(0xFFFFFFFFu, a, off);
        cnt += __shfl_xor_sync(0xFFFFFFFFu, cnt, off);
    }

    __shared__ float sa[THREADS / 32];
    __shared__ int   sc[THREADS / 32];
    __shared__ bool  s_last;
    const int wid = threadIdx.x >> 5;
    const int lid = threadIdx.x & 31;
    if (lid == 0) { sa[wid] = a; sc[wid] = cnt; }
    __syncthreads();

    if (threadIdx.x == 0) {
        float aa = sa[0] + sa[1] + sa[2] + sa[3] + sa[4] + sa[5] + sa[6] + sa[7];
        int   cc = sc[0] + sc[1] + sc[2] + sc[3] + sc[4] + sc[5] + sc[6] + sc[7];
        g_partial[blockIdx.x] = aa;
        g_count[blockIdx.x]   = cc;
        __threadfence();                                  // publish partials
        unsigned int old = atomicAdd(&g_ticket, 1u);
        s_last = (old == BLOCKS - 1);
    }
    __syncthreads();

    if (!s_last) return;

    // ---- last block: final reduction over 1024 partials, fixed order ----
    float s = 0.0f;
    int   c = 0;
#pragma unroll
    for (int i = 0; i < BLOCKS / THREADS; ++i) {          // 4 per thread
        const int idx = threadIdx.x + i * THREADS;
        s += g_partial[idx];
        c += g_count[idx];
    }
#pragma unroll
    for (int off = 16; off > 0; off >>= 1) {
        s += __shfl_xor_sync(0xFFFFFFFFu, s, off);
        c += __shfl_xor_sync(0xFFFFFFFFu, c, off);
    }
    __shared__ float fa[THREADS / 32];
    __shared__ int   fc[THREADS / 32];
    if (lid == 0) { fa[wid] = s; fc[wid] = c; }
    __syncthreads();
    if (threadIdx.x == 0) {
        float ss = fa[0] + fa[1] + fa[2] + fa[3] + fa[4] + fa[5] + fa[6] + fa[7];
        int   cc = fc[0] + fc[1] + fc[2] + fc[3] + fc[4] + fc[5] + fc[6] + fc[7];
        out[0] = -ss / (float)cc;
        g_ticket = 0;                                     // reset for next replay
    }
}

extern "C" void kernel_launch(void* const* d_in, const int* in_sizes, int n_in,
                              void* d_out, int out_size)
{
    const float* pred   = (const float*)d_in[0];
    const int*   target = (const int*)d_in[1];
    const int*   mask   = (const int*)d_in[2];
    float*       out    = (float*)d_out;

    ord_loss_fused<<<BLOCKS, THREADS>>>(pred, target, mask, out);
}